// round 1
// baseline (speedup 1.0000x reference)
#include <cuda_runtime.h>
#include <cstdint>
#include <cstddef>

// Problem constants
#define B_   2
#define L_   2048
#define D_   1024
#define H_   16
#define HD_  64
#define BL_  (B_ * L_)        // 4096
#define NBIAS_ 257            // 2*128+1

static const size_t OUT_ELEMS = (size_t)BL_ * D_;                 // 4,194,304
static const size_t ATT_ELEMS = (size_t)B_ * H_ * L_ * (size_t)L_; // 134,217,728

// Scratch (device globals: allocation-free rule)
__device__ float g_Q[BL_ * D_];
__device__ float g_K[BL_ * D_];
__device__ float g_V[BL_ * D_];
__device__ float g_ctx[BL_ * D_];
__device__ float g_attn[(size_t)B_ * H_ * L_ * (size_t)L_]; // fallback if attn not in d_out

// ---------------------------------------------------------------------------
// Classic 128x128x8 register-tiled fp32 GEMM:  C[M,N] = A[M,K] @ W[K,N] + bias
// ---------------------------------------------------------------------------
__global__ __launch_bounds__(256)
void sgemm_bias(const float* __restrict__ A, const float* __restrict__ W,
                const float* __restrict__ bias, float* __restrict__ C,
                int M, int N, int K)
{
    __shared__ float As[8][128];
    __shared__ float Bs[8][128];

    const int tid = threadIdx.x;
    const int bx = blockIdx.x;   // N tile
    const int by = blockIdx.y;   // M tile

    const int aRow = tid >> 1;          // 0..127
    const int aCol = (tid & 1) * 4;     // 0 or 4
    const int bRow = tid >> 5;          // 0..7
    const int bCol = (tid & 31) * 4;    // 0..124

    const int tx = tid & 15;            // 0..15 (cols, 8 each)
    const int ty = tid >> 4;            // 0..15 (rows, 8 each)

    const float* Ap = A + (size_t)(by * 128) * K;
    const float* Wp = W + bx * 128;

    float acc[8][8];
#pragma unroll
    for (int i = 0; i < 8; i++)
#pragma unroll
        for (int j = 0; j < 8; j++) acc[i][j] = 0.0f;

    for (int k0 = 0; k0 < K; k0 += 8) {
        float4 av = *(const float4*)(Ap + (size_t)aRow * K + k0 + aCol);
        As[aCol + 0][aRow] = av.x;
        As[aCol + 1][aRow] = av.y;
        As[aCol + 2][aRow] = av.z;
        As[aCol + 3][aRow] = av.w;
        *(float4*)&Bs[bRow][bCol] = *(const float4*)(Wp + (size_t)(k0 + bRow) * N + bCol);
        __syncthreads();
#pragma unroll
        for (int kk = 0; kk < 8; kk++) {
            float ar[8], br[8];
#pragma unroll
            for (int i = 0; i < 8; i++) ar[i] = As[kk][ty * 8 + i];
#pragma unroll
            for (int j = 0; j < 8; j++) br[j] = Bs[kk][tx * 8 + j];
#pragma unroll
            for (int i = 0; i < 8; i++)
#pragma unroll
                for (int j = 0; j < 8; j++) acc[i][j] += ar[i] * br[j];
        }
        __syncthreads();
    }

    const float* bp = bias + bx * 128 + tx * 8;
    float b0 = bp[0], b1 = bp[1], b2 = bp[2], b3 = bp[3];
    float b4 = bp[4], b5 = bp[5], b6 = bp[6], b7 = bp[7];
#pragma unroll
    for (int i = 0; i < 8; i++) {
        int row = by * 128 + ty * 8 + i;
        float* Cr = C + (size_t)row * N + bx * 128 + tx * 8;
        float4 v0 = make_float4(acc[i][0] + b0, acc[i][1] + b1, acc[i][2] + b2, acc[i][3] + b3);
        float4 v1 = make_float4(acc[i][4] + b4, acc[i][5] + b5, acc[i][6] + b6, acc[i][7] + b7);
        *(float4*)Cr = v0;
        *(float4*)(Cr + 4) = v1;
    }
}

// ---------------------------------------------------------------------------
// Scores: S[b,h,q,k] = (Q . K)/8 + rel_bias[clip(k-q)+128, h]
// Batched 128x128 tile GEMM with K-dim = 64, reading strided head slices.
// ---------------------------------------------------------------------------
__global__ __launch_bounds__(256)
void scores_kernel(const float* __restrict__ rel_bias, float* __restrict__ attn)
{
    __shared__ float As[8][128];
    __shared__ float Bs[8][128];
    __shared__ float sb[NBIAS_];

    const int tid = threadIdx.x;
    const int bx = blockIdx.x;   // k tile (of 16)
    const int by = blockIdx.y;   // q tile (of 16)
    const int bh = blockIdx.z;   // 0..31
    const int b = bh >> 4;
    const int h = bh & 15;

    for (int i = tid; i < NBIAS_; i += 256) sb[i] = rel_bias[i * H_ + h];

    const int aRow = tid >> 1;         // 0..127
    const int aCol = (tid & 1) * 4;    // 0 or 4
    const int tx = tid & 15;
    const int ty = tid >> 4;

    const float* Qb = g_Q + (size_t)(b * L_ + by * 128) * D_ + h * HD_;
    const float* Kb = g_K + (size_t)(b * L_ + bx * 128) * D_ + h * HD_;

    float acc[8][8];
#pragma unroll
    for (int i = 0; i < 8; i++)
#pragma unroll
        for (int j = 0; j < 8; j++) acc[i][j] = 0.0f;

    for (int k0 = 0; k0 < HD_; k0 += 8) {
        float4 av = *(const float4*)(Qb + (size_t)aRow * D_ + k0 + aCol);
        As[aCol + 0][aRow] = av.x;
        As[aCol + 1][aRow] = av.y;
        As[aCol + 2][aRow] = av.z;
        As[aCol + 3][aRow] = av.w;
        float4 bv = *(const float4*)(Kb + (size_t)aRow * D_ + k0 + aCol);
        Bs[aCol + 0][aRow] = bv.x;
        Bs[aCol + 1][aRow] = bv.y;
        Bs[aCol + 2][aRow] = bv.z;
        Bs[aCol + 3][aRow] = bv.w;
        __syncthreads();
#pragma unroll
        for (int kk = 0; kk < 8; kk++) {
            float ar[8], br[8];
#pragma unroll
            for (int i = 0; i < 8; i++) ar[i] = As[kk][ty * 8 + i];
#pragma unroll
            for (int j = 0; j < 8; j++) br[j] = Bs[kk][tx * 8 + j];
#pragma unroll
            for (int i = 0; i < 8; i++)
#pragma unroll
                for (int j = 0; j < 8; j++) acc[i][j] += ar[i] * br[j];
        }
        __syncthreads();
    }

    const float scale = 0.125f;   // 1/sqrt(64)
#pragma unroll
    for (int i = 0; i < 8; i++) {
        int q = by * 128 + ty * 8 + i;
        int kc0 = bx * 128 + tx * 8;
        float* out = attn + ((size_t)bh * L_ + q) * L_ + kc0;
        float v[8];
#pragma unroll
        for (int j = 0; j < 8; j++) {
            int rel = kc0 + j - q;
            rel = rel < -128 ? -128 : (rel > 128 ? 128 : rel);
            v[j] = acc[i][j] * scale + sb[rel + 128];
        }
        *(float4*)out = make_float4(v[0], v[1], v[2], v[3]);
        *(float4*)(out + 4) = make_float4(v[4], v[5], v[6], v[7]);
    }
}

// ---------------------------------------------------------------------------
// Row softmax over Lk=2048, in place. One block per row, 256 threads x 8 elems
// ---------------------------------------------------------------------------
__device__ __forceinline__ float warpMax(float v) {
#pragma unroll
    for (int o = 16; o > 0; o >>= 1) v = fmaxf(v, __shfl_xor_sync(0xffffffffu, v, o));
    return v;
}
__device__ __forceinline__ float warpSum(float v) {
#pragma unroll
    for (int o = 16; o > 0; o >>= 1) v += __shfl_xor_sync(0xffffffffu, v, o);
    return v;
}

__global__ __launch_bounds__(256)
void softmax_kernel(float* __restrict__ attn)
{
    __shared__ float sm[8];
    __shared__ float ss[8];

    const size_t row = blockIdx.x;
    float* p = attn + row * (size_t)L_;
    const int tid = threadIdx.x;
    const int lane = tid & 31;
    const int warp = tid >> 5;

    float4 v0 = ((const float4*)p)[tid];
    float4 v1 = ((const float4*)p)[tid + 256];

    float m = fmaxf(fmaxf(fmaxf(v0.x, v0.y), fmaxf(v0.z, v0.w)),
                    fmaxf(fmaxf(v1.x, v1.y), fmaxf(v1.z, v1.w)));
    m = warpMax(m);
    if (lane == 0) sm[warp] = m;
    __syncthreads();
    if (warp == 0) {
        float t = (lane < 8) ? sm[lane] : -3.4e38f;
        t = warpMax(t);
        if (lane == 0) sm[0] = t;
    }
    __syncthreads();
    m = sm[0];

    v0.x = __expf(v0.x - m); v0.y = __expf(v0.y - m);
    v0.z = __expf(v0.z - m); v0.w = __expf(v0.w - m);
    v1.x = __expf(v1.x - m); v1.y = __expf(v1.y - m);
    v1.z = __expf(v1.z - m); v1.w = __expf(v1.w - m);

    float s = (v0.x + v0.y) + (v0.z + v0.w) + (v1.x + v1.y) + (v1.z + v1.w);
    s = warpSum(s);
    if (lane == 0) ss[warp] = s;
    __syncthreads();
    if (warp == 0) {
        float t = (lane < 8) ? ss[lane] : 0.0f;
        t = warpSum(t);
        if (lane == 0) ss[0] = t;
    }
    __syncthreads();
    float inv = 1.0f / ss[0];

    v0.x *= inv; v0.y *= inv; v0.z *= inv; v0.w *= inv;
    v1.x *= inv; v1.y *= inv; v1.z *= inv; v1.w *= inv;
    ((float4*)p)[tid] = v0;
    ((float4*)p)[tid + 256] = v1;
}

// ---------------------------------------------------------------------------
// PV: ctx[b, q, h*64+d] = sum_k P[b,h,q,k] * V[b, k, h*64+d]
// 128(q) x 64(d) tiles, K-chunk 16 over Lk=2048
// ---------------------------------------------------------------------------
__global__ __launch_bounds__(256)
void av_kernel(const float* __restrict__ attn)
{
    __shared__ float Ps[16][128];
    __shared__ float Vs[16][64];

    const int tid = threadIdx.x;
    const int by = blockIdx.x;   // q tile, 0..15
    const int bh = blockIdx.y;   // 0..31
    const int b = bh >> 4;
    const int h = bh & 15;

    const int pRow = tid >> 1;          // 0..127 (q)
    const int pCol = (tid & 1) * 8;     // 0 or 8 (k)
    const int vRow = tid >> 4;          // 0..15 (k)
    const int vCol = (tid & 15) * 4;    // 0..60 (d)

    const int tx = tid & 15;            // d groups of 4
    const int ty = tid >> 4;            // q groups of 8

    const float* Pb = attn + ((size_t)bh * L_ + by * 128) * L_;
    const float* Vb = g_V + (size_t)(b * L_) * D_ + h * HD_;

    float acc[8][4];
#pragma unroll
    for (int i = 0; i < 8; i++)
#pragma unroll
        for (int j = 0; j < 4; j++) acc[i][j] = 0.0f;

    for (int k0 = 0; k0 < L_; k0 += 16) {
        float4 p0 = *(const float4*)(Pb + (size_t)pRow * L_ + k0 + pCol);
        float4 p1 = *(const float4*)(Pb + (size_t)pRow * L_ + k0 + pCol + 4);
        Ps[pCol + 0][pRow] = p0.x;
        Ps[pCol + 1][pRow] = p0.y;
        Ps[pCol + 2][pRow] = p0.z;
        Ps[pCol + 3][pRow] = p0.w;
        Ps[pCol + 4][pRow] = p1.x;
        Ps[pCol + 5][pRow] = p1.y;
        Ps[pCol + 6][pRow] = p1.z;
        Ps[pCol + 7][pRow] = p1.w;
        *(float4*)&Vs[vRow][vCol] = *(const float4*)(Vb + (size_t)(k0 + vRow) * D_ + vCol);
        __syncthreads();
#pragma unroll
        for (int kk = 0; kk < 16; kk++) {
            float ar[8], br[4];
#pragma unroll
            for (int i = 0; i < 8; i++) ar[i] = Ps[kk][ty * 8 + i];
#pragma unroll
            for (int j = 0; j < 4; j++) br[j] = Vs[kk][tx * 4 + j];
#pragma unroll
            for (int i = 0; i < 8; i++)
#pragma unroll
                for (int j = 0; j < 4; j++) acc[i][j] += ar[i] * br[j];
        }
        __syncthreads();
    }

#pragma unroll
    for (int i = 0; i < 8; i++) {
        int q = by * 128 + ty * 8 + i;
        float* out = g_ctx + (size_t)(b * L_ + q) * D_ + h * HD_ + tx * 4;
        *(float4*)out = make_float4(acc[i][0], acc[i][1], acc[i][2], acc[i][3]);
    }
}

// ---------------------------------------------------------------------------
extern "C" void kernel_launch(void* const* d_in, const int* in_sizes, int n_in,
                              void* d_out, int out_size)
{
    const float* query = (const float*)d_in[0];
    const float* key_  = (const float*)d_in[1];
    const float* value = (const float*)d_in[2];
    const float* Wq = (const float*)d_in[3];
    const float* bq = (const float*)d_in[4];
    const float* Wk = (const float*)d_in[5];
    const float* bk = (const float*)d_in[6];
    const float* Wv = (const float*)d_in[7];
    const float* bv = (const float*)d_in[8];
    const float* Wo = (const float*)d_in[9];
    const float* bo = (const float*)d_in[10];
    const float* rel_bias = (const float*)d_in[11];
    float* outp = (float*)d_out;

    // Resolve scratch symbol addresses (not stream ops; capture-safe)
    static float *Qp = nullptr, *Kp = nullptr, *Vp = nullptr, *Cp = nullptr, *Ap = nullptr;
    if (!Qp) {
        cudaGetSymbolAddress((void**)&Qp, g_Q);
        cudaGetSymbolAddress((void**)&Kp, g_K);
        cudaGetSymbolAddress((void**)&Vp, g_V);
        cudaGetSymbolAddress((void**)&Cp, g_ctx);
        cudaGetSymbolAddress((void**)&Ap, g_attn);
    }

    // Attention matrix: second output if the harness expects it, else scratch.
    float* attn = ((size_t)out_size >= OUT_ELEMS + ATT_ELEMS) ? (outp + OUT_ELEMS) : Ap;

    dim3 gProj(D_ / 128, BL_ / 128);       // (8, 32)
    sgemm_bias<<<gProj, 256>>>(query, Wq, bq, Qp, BL_, D_, D_);
    sgemm_bias<<<gProj, 256>>>(key_,  Wk, bk, Kp, BL_, D_, D_);
    sgemm_bias<<<gProj, 256>>>(value, Wv, bv, Vp, BL_, D_, D_);

    dim3 gScores(L_ / 128, L_ / 128, B_ * H_);  // (16, 16, 32)
    scores_kernel<<<gScores, 256>>>(rel_bias, attn);

    softmax_kernel<<<(unsigned)(B_ * H_ * L_), 256>>>(attn);  // 65536 rows

    dim3 gAV(L_ / 128, B_ * H_);            // (16, 32)
    av_kernel<<<gAV, 256>>>(attn);

    sgemm_bias<<<gProj, 256>>>(Cp, Wo, bo, outp, BL_, D_, D_);
}